// round 1
// baseline (speedup 1.0000x reference)
#include <cuda_runtime.h>
#include <cstdint>

#define BATCH 64
#define NTOK  65536            // 256*256
#define KSEL  16384
#define TOTAL (BATCH * NTOK)

// ---- scratch (no allocations allowed) ----
__device__ uint32_t g_T[BATCH];      // 32-bit threshold bit pattern per batch
__device__ uint32_t g_req[BATCH];    // how many ==T elements to include
__device__ uint32_t g_eqcnt[BATCH];  // runtime tie counter
__device__ double   g_acc;           // loss accumulator

__global__ void init_kernel() {
    int t = threadIdx.x;
    if (t < BATCH) g_eqcnt[t] = 0u;
    if (t == 0)    g_acc = 0.0;
}

// One CTA per batch: 3-pass radix select (12+12+8 bits) on float bit patterns.
// s_map values are uniform [0,1) -> positive floats -> uint ordering == value ordering.
__global__ __launch_bounds__(1024) void select_kernel(const float* __restrict__ smap) {
    __shared__ uint32_t hist[4096];
    __shared__ uint32_t part[1024];
    __shared__ uint32_t sFoundBin, sFoundK;

    const int b = blockIdx.x;
    const int t = threadIdx.x;
    const uint32_t* __restrict__ data =
        reinterpret_cast<const uint32_t*>(smap) + (size_t)b * NTOK;

    uint32_t prefix = 0;
    uint32_t Kcur   = KSEL;

    const int shifts[3] = {20, 8, 0};
    const int nbitsA[3] = {12, 12, 8};

    for (int pass = 0; pass < 3; pass++) {
        const int shift = shifts[pass];
        const int nbits = nbitsA[pass];
        const int nbins = 1 << nbits;
        const int hi_shift = shift + nbits;     // 32 on pass 0 (never used then)

        for (int i = t; i < nbins; i += 1024) hist[i] = 0u;
        __syncthreads();

        for (int i = t; i < NTOK; i += 1024) {
            uint32_t u = data[i];
            bool match = (pass == 0) || ((u >> hi_shift) == prefix);
            if (match) atomicAdd(&hist[(u >> shift) & (uint32_t)(nbins - 1)], 1u);
        }
        __syncthreads();

        // per-thread partial over its bin chunk
        const int bpt  = (nbins + 1023) >> 10;   // 4 or 1
        const int base = t * bpt;
        uint32_t p = 0;
        for (int j = 0; j < bpt; j++) {
            int idx = base + j;
            if (idx < nbins) p += hist[idx];
        }
        part[t] = p;
        __syncthreads();

        // inclusive suffix scan over 1024 partials (Hillis-Steele)
        for (int off = 1; off < 1024; off <<= 1) {
            uint32_t v = (t + off < 1024) ? part[t + off] : 0u;
            __syncthreads();
            part[t] += v;
            __syncthreads();
        }
        // part[t] = sum of partials for threads >= t
        uint32_t beyond = (t < 1023) ? part[t + 1] : 0u;

        // locate boundary bin: suffix(b*) >= Kcur > suffix(b*+1)
        uint32_t sfx = beyond;
        for (int j = bpt - 1; j >= 0; j--) {
            int idx = base + j;
            if (idx < nbins) {
                uint32_t s_incl = sfx + hist[idx];
                if (s_incl >= Kcur && sfx < Kcur) {
                    sFoundBin = (uint32_t)idx;
                    sFoundK   = Kcur - sfx;     // still needed from this bin
                }
                sfx = s_incl;
            }
        }
        __syncthreads();
        prefix = (prefix << nbits) | sFoundBin;
        Kcur   = sFoundK;
        __syncthreads();   // hist reused next pass
    }

    if (t == 0) { g_T[b] = prefix; g_req[b] = Kcur; }
}

// Grid-stride loss: term = min(softplus(+-d), 100), summed in double.
__global__ __launch_bounds__(256) void loss_kernel(const float2* __restrict__ zs,
                                                   const float*  __restrict__ smap,
                                                   const float2* __restrict__ gn) {
    __shared__ double ssum[256];
    double acc = 0.0;
    const int stride = gridDim.x * blockDim.x;
    for (int i = blockIdx.x * blockDim.x + threadIdx.x; i < TOTAL; i += stride) {
        const int b = i >> 16;
        const uint32_t u = __float_as_uint(smap[i]);
        const uint32_t T = g_T[b];
        bool sel;
        if (u > T)       sel = true;
        else if (u == T) sel = (atomicAdd(&g_eqcnt[b], 1u) < g_req[b]);
        else             sel = false;

        const float2 z = zs[i];
        const float2 g = gn[i];
        const float d = (z.x + g.x) - (z.y + g.y);
        const float x = sel ? -d : d;
        // softplus(x), numerically stable
        float sp = (x > 0.0f) ? (x + log1pf(expf(-x))) : log1pf(expf(x));
        sp = fminf(sp, 100.0f);     // == torch BCE log-clamp at -100
        acc += (double)sp;
    }

    ssum[threadIdx.x] = acc;
    __syncthreads();
    for (int s = 128; s > 0; s >>= 1) {
        if (threadIdx.x < s) ssum[threadIdx.x] += ssum[threadIdx.x + s];
        __syncthreads();
    }
    if (threadIdx.x == 0) atomicAdd(&g_acc, ssum[0]);
}

__global__ void finalize_kernel(float* __restrict__ out) {
    out[0] = (float)g_acc;
}

extern "C" void kernel_launch(void* const* d_in, const int* in_sizes, int n_in,
                              void* d_out, int out_size) {
    const float* scores = (const float*)d_in[0];   // [B, N, 2]
    const float* smap   = (const float*)d_in[1];   // [B, 1, H, W] == [B, N]
    const float* gumb   = (const float*)d_in[2];   // [B, N, 2]
    float* out = (float*)d_out;

    init_kernel<<<1, 64>>>();
    select_kernel<<<BATCH, 1024>>>(smap);
    loss_kernel<<<4096, 256>>>((const float2*)scores, smap, (const float2*)gumb);
    finalize_kernel<<<1, 1>>>(out);
}

// round 2
// speedup vs baseline: 1.3757x; 1.3757x over previous
#include <cuda_runtime.h>
#include <cstdint>

#define BATCH 64
#define NTOK  65536            // 256*256
#define KSEL  16384
#define TOTAL (BATCH * NTOK)
#define NGRP  (TOTAL / 4)      // 4 tokens per group
#define CAP   16384            // candidate capacity (smem)

// ---- device scratch (no allocations allowed) ----
__device__ uint32_t g_T[BATCH];      // 32-bit threshold bit pattern per batch
__device__ uint32_t g_req[BATCH];    // how many ==T elements to include
__device__ uint32_t g_eqcnt[BATCH];  // runtime tie counter
__device__ double   g_acc;           // loss accumulator
__device__ unsigned g_done;          // finished-block ticket

// Sum of v over all threads with tid' > tid (blockDim == 1024).
// wsum: shared uint32_t[32]. Caller must separate successive calls with a sync
// that orders any wsum reuse (the radix rounds' hist-zero sync does this).
__device__ __forceinline__ uint32_t suffix_excl_1024(uint32_t v, uint32_t* wsum) {
    const int lane = threadIdx.x & 31;
    const int w    = threadIdx.x >> 5;
    uint32_t s = v;                       // inclusive suffix within warp
    #pragma unroll
    for (int off = 1; off < 32; off <<= 1) {
        uint32_t o = __shfl_down_sync(0xFFFFFFFFu, s, off);
        if (lane + off < 32) s += o;
    }
    if (lane == 0) wsum[w] = s;           // warp total
    __syncthreads();
    if (threadIdx.x < 32) {
        uint32_t x  = wsum[threadIdx.x];
        uint32_t sx = x;
        #pragma unroll
        for (int off = 1; off < 32; off <<= 1) {
            uint32_t o = __shfl_down_sync(0xFFFFFFFFu, sx, off);
            if (lane + off < 32) sx += o;
        }
        wsum[threadIdx.x] = sx - x;       // exclusive suffix of warp sums
    }
    __syncthreads();
    return wsum[w] + (s - v);
}

// One CTA per batch. Pivot-window select:
//  pass: count c2 = #{u >= P2} (ballot, no atomics), gather P1<=u<P2 into smem.
//  then exact radix select among candidates for rank (K - c2).
// s_map uniform [0,1) -> positive floats -> uint ordering == value ordering.
__global__ __launch_bounds__(1024) void select_kernel(const float* __restrict__ smap) {
    extern __shared__ uint32_t dyn[];
    uint32_t* cand = dyn;                 // [CAP]
    uint32_t* hist = dyn + CAP;           // [2048]
    uint32_t* wsum = dyn + CAP + 2048;    // [32]
    __shared__ uint32_t sNc, sC2, sBin, sK;

    const int b = blockIdx.x;
    const int t = threadIdx.x;
    const int lane = t & 31;

    // fused init for the loss kernel (reset every graph replay)
    if (t == 0) {
        g_eqcnt[b] = 0u;
        if (b == 0) { g_acc = 0.0; g_done = 0u; }
    }

    const uint4* __restrict__ data4 =
        reinterpret_cast<const uint4*>(smap + (size_t)b * NTOK);   // 16384 uint4

    float lo = 0.73f, hi = 0.77f;
    uint32_t c2 = 0, ncand = 0;

    for (int attempt = 0; attempt < 8; attempt++) {
        const uint32_t P1 = __float_as_uint(lo);
        const uint32_t P2 = __float_as_uint(hi);
        if (t == 0) sNc = 0u;
        __syncthreads();

        uint32_t cnt = 0;
        #pragma unroll 4
        for (int i = t; i < NTOK / 4; i += 1024) {
            uint4 v = data4[i];
            #pragma unroll
            for (int c = 0; c < 4; c++) {
                uint32_t u = (c == 0) ? v.x : (c == 1) ? v.y : (c == 2) ? v.z : v.w;
                cnt += (u >= P2);
                bool isC = (u >= P1) && (u < P2);
                unsigned m = __ballot_sync(0xFFFFFFFFu, isC);
                if (m) {
                    int leader = __ffs(m) - 1;
                    uint32_t base = 0;
                    if (lane == leader) base = atomicAdd(&sNc, (uint32_t)__popc(m));
                    base = __shfl_sync(0xFFFFFFFFu, base, leader);
                    if (isC) {
                        uint32_t idx = base + __popc(m & ((1u << lane) - 1u));
                        if (idx < CAP) cand[idx] = u;
                    }
                }
            }
        }
        // block total of cnt
        uint32_t ex = suffix_excl_1024(cnt, wsum);
        if (t == 0) sC2 = ex + cnt;
        __syncthreads();
        c2 = sC2; ncand = sNc;
        if (c2 < KSEL && KSEL <= c2 + ncand && ncand <= CAP) break;   // window hit
        lo -= 0.05f * (float)(attempt + 1); if (lo < 0.0f) lo = 0.0f;
        hi += 0.05f * (float)(attempt + 1); if (hi > 0.999999f) hi = 0.999999f;
        __syncthreads();   // protect sNc/wsum reset
    }

    // exact radix select among cand[0..ncand) for rank Kcur (from the top)
    uint32_t Kcur = KSEL - c2;
    uint32_t prefixVal = 0;

    const int shifts[3]  = {21, 10, 0};
    const int nbitsA[3]  = {11, 11, 10};
    #pragma unroll
    for (int r = 0; r < 3; r++) {
        const int shift = shifts[r];
        const int nbits = nbitsA[r];
        const int nbins = 1 << nbits;
        const int hishift = shift + nbits;      // 32 on round 0 (unused then)

        for (int i = t; i < nbins; i += 1024) hist[i] = 0u;
        __syncthreads();
        for (uint32_t i = t; i < ncand; i += 1024) {
            uint32_t u = cand[i];
            bool match = (r == 0) || ((u >> hishift) == prefixVal);
            if (match) atomicAdd(&hist[(u >> shift) & (uint32_t)(nbins - 1)], 1u);
        }
        __syncthreads();

        const int bpt  = (nbins + 1023) >> 10;  // 2 or 1
        const int base = t * bpt;
        uint32_t p = 0;
        for (int j = 0; j < bpt; j++) { int idx = base + j; if (idx < nbins) p += hist[idx]; }
        uint32_t sfx = suffix_excl_1024(p, wsum);   // bins above my chunk
        for (int j = bpt - 1; j >= 0; j--) {
            int idx = base + j;
            if (idx < nbins) {
                uint32_t s_incl = sfx + hist[idx];
                if (sfx < Kcur && s_incl >= Kcur) { sBin = (uint32_t)idx; sK = Kcur - sfx; }
                sfx = s_incl;
            }
        }
        __syncthreads();
        prefixVal = (prefixVal << nbits) | sBin;
        Kcur = sK;
        __syncthreads();
    }

    if (t == 0) { g_T[b] = prefixVal; g_req[b] = Kcur; }
}

// loss term: sel ? softplus(-d) : softplus(d), clamped at 100.
// softplus(x) = ln(1+e^{-|x|}) + max(x,0); max(-d,0) = max(d,0) - d.
__device__ __forceinline__ float term(float d, uint32_t u, uint32_t T, int b) {
    bool sel;
    if (u > T)       sel = true;
    else if (u == T) sel = (atomicAdd(&g_eqcnt[b], 1u) < g_req[b]);   // rare
    else             sel = false;
    float c = __logf(1.0f + __expf(-fabsf(d)));
    float v = c + fmaxf(d, 0.0f) - (sel ? d : 0.0f);
    return fminf(v, 100.0f);
}

__global__ __launch_bounds__(256) void loss_kernel(const float4* __restrict__ zs4,
                                                   const uint4*  __restrict__ sm4,
                                                   const float4* __restrict__ gn4,
                                                   float* __restrict__ out) {
    double acc = 0.0;
    const int stride = gridDim.x * blockDim.x;
    for (int g = blockIdx.x * blockDim.x + threadIdx.x; g < NGRP; g += stride) {
        const int b = g >> 14;                 // 16384 groups per batch
        const uint32_t T = g_T[b];
        uint4  u  = sm4[g];
        float4 za = zs4[2 * g], zb = zs4[2 * g + 1];
        float4 ga = gn4[2 * g], gb = gn4[2 * g + 1];
        float d0 = (za.x + ga.x) - (za.y + ga.y);
        float d1 = (za.z + ga.z) - (za.w + ga.w);
        float d2 = (zb.x + gb.x) - (zb.y + gb.y);
        float d3 = (zb.z + gb.z) - (zb.w + gb.w);
        float s = (term(d0, u.x, T, b) + term(d1, u.y, T, b))
                + (term(d2, u.z, T, b) + term(d3, u.w, T, b));
        acc += (double)s;
    }

    // block reduce (8 warps) in double
    __shared__ double wpart[8];
    const int lane = threadIdx.x & 31, w = threadIdx.x >> 5;
    #pragma unroll
    for (int off = 16; off > 0; off >>= 1)
        acc += __shfl_down_sync(0xFFFFFFFFu, acc, off);
    if (lane == 0) wpart[w] = acc;
    __syncthreads();
    if (threadIdx.x == 0) {
        double bsum = 0.0;
        #pragma unroll
        for (int i = 0; i < 8; i++) bsum += wpart[i];
        atomicAdd(&g_acc, bsum);
        __threadfence();
        unsigned ticket = atomicAdd(&g_done, 1u);
        if (ticket == gridDim.x - 1) {          // last block: fused finalize
            __threadfence();
            out[0] = (float)atomicAdd(&g_acc, 0.0);
        }
    }
}

extern "C" void kernel_launch(void* const* d_in, const int* in_sizes, int n_in,
                              void* d_out, int out_size) {
    const float* scores = (const float*)d_in[0];   // [B, N, 2]
    const float* smap   = (const float*)d_in[1];   // [B, 1, H, W] == [B, N]
    const float* gumb   = (const float*)d_in[2];   // [B, N, 2]
    float* out = (float*)d_out;

    const int smem_bytes = (CAP + 2048 + 32) * (int)sizeof(uint32_t);   // ~73.9 KB
    cudaFuncSetAttribute(select_kernel, cudaFuncAttributeMaxDynamicSharedMemorySize, smem_bytes);

    select_kernel<<<BATCH, 1024, smem_bytes>>>(smap);
    loss_kernel<<<4096, 256>>>((const float4*)scores, (const uint4*)smap,
                               (const float4*)gumb, out);
}